// round 4
// baseline (speedup 1.0000x reference)
#include <cuda_runtime.h>

#define SEQ 2048
#define BATCH 1024
#define NL 6
#define UF 8
#define MASK 0x0FFFFFFFu   // lanes 0..27 active

typedef unsigned long long ull;

__device__ __forceinline__ float tanh_ap(float x) {
    float y;
    asm("tanh.approx.f32 %0, %1;" : "=f"(y) : "f"(x));
    return y;
}
__device__ __forceinline__ ull pk(float lo, float hi) {
    ull r;
    asm("mov.b64 %0, {%1, %2};" : "=l"(r) : "f"(lo), "f"(hi));
    return r;
}
__device__ __forceinline__ void upk(float& lo, float& hi, ull v) {
    asm("mov.b64 {%0, %1}, %2;" : "=f"(lo), "=f"(hi) : "l"(v));
}
// Packed dual-FMA: (d.lo,d.hi) = (a.lo*b.lo+c.lo, a.hi*b.hi+c.hi)
__device__ __forceinline__ ull fma2(ull a, ull b, ull c) {
    ull d;
    asm("fma.rn.f32x2 %0, %1, %2, %3;" : "=l"(d) : "l"(a), "l"(b), "l"(c));
    return d;
}
// Predicated store, no BSSY/BSYNC.
__device__ __forceinline__ void store_pred(int flag, float* p, float v) {
    asm volatile(
        "{\n\t.reg .pred %%pp;\n\t"
        "setp.ne.s32 %%pp, %0, 0;\n\t"
        "@%%pp st.global.f32 [%1], %2;\n\t}"
        :: "r"(flag), "l"(p), "f"(v) : "memory");
}

struct LaneState {
    ull wi_if[4], wi_go[4];   // packed (i,f) / (g,o) input weights, pre-scaled
    ull wh_if[4], wh_go[4];   // packed recurrent weights, pre-scaled
    ull b_if, b_go;           // packed biases (pre-scaled)
    float h, c2;              // h holds 2*h_true (feeder: x); c2 = 2*c_true
    float rw0, rw1, rw2, rw3, rb;
    int lane, l, bh, bi, b;
    int isfeed, headflag;
};

template<bool Guarded>
__device__ __forceinline__ void tick(int k, LaneState& s, float& xslot,
                                     const float* __restrict__ xptr,
                                     float* __restrict__ out)
{
    // Cross-lane h (values are 2h; weights pre-halved).
    const float hv0 = __shfl_sync(MASK, s.h, s.bh + 0);
    const float hv1 = __shfl_sync(MASK, s.h, s.bh + 1);
    const float hv2 = __shfl_sync(MASK, s.h, s.bh + 2);
    const float hv3 = __shfl_sync(MASK, s.h, s.bh + 3);
    const float iv0 = __shfl_sync(MASK, s.h, s.bi + 0);
    const float iv1 = __shfl_sync(MASK, s.h, s.bi + 1);
    const float iv2 = __shfl_sync(MASK, s.h, s.bi + 2);
    const float iv3 = __shfl_sync(MASK, s.h, s.bi + 3);

    // Linear head (rw pre-scaled by 0.5).
    float y = s.rb;
    y = fmaf(s.rw0, hv0, y);
    y = fmaf(s.rw1, hv1, y);
    y = fmaf(s.rw2, hv2, y);
    y = fmaf(s.rw3, hv3, y);
    const int t_out = k - NL;
    const int t_ok = Guarded ? ((unsigned)t_out < SEQ) : 1;
    const int t_clamped = Guarded ? (t_out < 0 ? 0 : (t_out >= SEQ ? SEQ - 1 : t_out)) : t_out;
    store_pred(s.headflag & t_ok, out + (size_t)t_clamped * BATCH + s.b, y);

    // Packed gate dots: (i,f) and (g,o) accumulate through one 8-step chain;
    // iv steps first (off critical path), hv steps last.
    const ull dv_i0 = pk(iv0, iv0), dv_i1 = pk(iv1, iv1);
    const ull dv_i2 = pk(iv2, iv2), dv_i3 = pk(iv3, iv3);
    const ull dv_h0 = pk(hv0, hv0), dv_h1 = pk(hv1, hv1);
    const ull dv_h2 = pk(hv2, hv2), dv_h3 = pk(hv3, hv3);

    ull acc_if = s.b_if, acc_go = s.b_go;
    acc_if = fma2(s.wi_if[0], dv_i0, acc_if); acc_go = fma2(s.wi_go[0], dv_i0, acc_go);
    acc_if = fma2(s.wi_if[1], dv_i1, acc_if); acc_go = fma2(s.wi_go[1], dv_i1, acc_go);
    acc_if = fma2(s.wi_if[2], dv_i2, acc_if); acc_go = fma2(s.wi_go[2], dv_i2, acc_go);
    acc_if = fma2(s.wi_if[3], dv_i3, acc_if); acc_go = fma2(s.wi_go[3], dv_i3, acc_go);
    acc_if = fma2(s.wh_if[0], dv_h0, acc_if); acc_go = fma2(s.wh_go[0], dv_h0, acc_go);
    acc_if = fma2(s.wh_if[1], dv_h1, acc_if); acc_go = fma2(s.wh_go[1], dv_h1, acc_go);
    acc_if = fma2(s.wh_if[2], dv_h2, acc_if); acc_go = fma2(s.wh_go[2], dv_h2, acc_go);
    acc_if = fma2(s.wh_if[3], dv_h3, acc_if); acc_go = fma2(s.wh_go[3], dv_h3, acc_go);

    float gi, gf, gg, go;
    upk(gi, gf, acc_if);
    upk(gg, go, acc_go);

    const float ti = tanh_ap(gi);   // tanh(0.5*pre_i) = 2*sigm(pre_i)-1
    const float tf = tanh_ap(gf);
    const float cc = tanh_ap(gg);   // tanh(pre_g)
    const float to = tanh_ap(go);

    // c2 = 2c:  u = tf*c2 + c2 = 2(sf-part*2...)  v = ti*cc + cc
    // c2_new = 0.5*u + v   (one packed fma computes u,v together)
    const ull uv = fma2(pk(tf, ti), pk(s.c2, cc), pk(s.c2, cc));
    float u, v;
    upk(u, v, uv);
    const float nc2 = fmaf(0.5f, u, v);
    const float th  = tanh_ap(0.5f * nc2);
    const float nh  = fmaf(to, th, th);          // 2*h_new

    const float xv = xslot;
    xslot = __ldg(xptr);

    if (Guarded) {
        const int valid = ((unsigned)(k - s.l) < SEQ);
        const float nh2 = valid ? nh : s.h;
        const float nc2b = valid ? nc2 : s.c2;
        s.h  = s.isfeed ? xv : nh2;
        s.c2 = s.isfeed ? s.c2 : nc2b;
    } else {
        s.h  = s.isfeed ? xv : nh;
        s.c2 = nc2;   // feeder's c2 is inert; harmless
    }
}

__global__ __launch_bounds__(256) void lstm_reg_kernel(
    const float* __restrict__ x,      // [S, B, 4]
    const float* __restrict__ w_ih,   // [6, 16, 4]
    const float* __restrict__ w_hh,   // [6, 16, 4]
    const float* __restrict__ b_ih,   // [6, 16]
    const float* __restrict__ b_hh,   // [6, 16]
    const float* __restrict__ reg_w,  // [1, 4]
    const float* __restrict__ reg_b,  // [1]
    float* __restrict__ out)          // [S, B, 1]
{
    const int lane = threadIdx.x & 31;
    const int warp = threadIdx.x >> 5;
    if (lane >= 28) return;

    LaneState s;
    s.lane = lane;
    s.b = blockIdx.x * 8 + warp;
    s.l = lane >> 2;                     // 0..5 layers, 6 = x feeder
    const int j = lane & 3;
    s.bh = s.l * 4;
    s.bi = (s.l == 0) ? 24 : (s.l - 1) * 4;
    s.isfeed = (s.l == 6);
    s.headflag = (lane == 20);

    float wi[4][4], wh[4][4], bb[4];
#pragma unroll
    for (int g = 0; g < 4; ++g) {
#pragma unroll
        for (int i = 0; i < 4; ++i) { wi[g][i] = 0.f; wh[g][i] = 0.f; }
        bb[g] = 0.f;
    }
    if (s.l < 6) {
#pragma unroll
        for (int g = 0; g < 4; ++g) {
            const int row = s.l * 16 + g * 4 + j;       // gate order i,f,g,o
            const float gsc = (g == 2) ? 1.0f : 0.5f;   // sigmoid-as-tanh fold
            const float isc = (s.l == 0) ? 1.0f : 0.5f; // input is 2h for layers>0
#pragma unroll
            for (int i = 0; i < 4; ++i) {
                wi[g][i] = w_ih[row * 4 + i] * gsc * isc;
                wh[g][i] = w_hh[row * 4 + i] * gsc * 0.5f;  // own h is 2h
            }
            bb[g] = (b_ih[row] + b_hh[row]) * gsc;
        }
    }
#pragma unroll
    for (int m = 0; m < 4; ++m) {
        s.wi_if[m] = pk(wi[0][m], wi[1][m]);
        s.wi_go[m] = pk(wi[2][m], wi[3][m]);
        s.wh_if[m] = pk(wh[0][m], wh[1][m]);
        s.wh_go[m] = pk(wh[2][m], wh[3][m]);
    }
    s.b_if = pk(bb[0], bb[1]);
    s.b_go = pk(bb[2], bb[3]);

    s.rw0 = reg_w[0] * 0.5f; s.rw1 = reg_w[1] * 0.5f;
    s.rw2 = reg_w[2] * 0.5f; s.rw3 = reg_w[3] * 0.5f;
    s.rb  = reg_b[0];

    s.h = 0.f; s.c2 = 0.f;
    const float* xq = x + (size_t)s.b * 4 + j;
    if (s.isfeed) s.h = xq[0];           // feeder starts with x[0] (raw x;
                                         // layer-0 wih unscaled by isc)

    // Prefetch ring: slot u holds x[tick+1] for tick ≡ u (mod UF).
    float xbuf[UF];
#pragma unroll
    for (int u = 0; u < UF; ++u) {
        const int idx = (u + 1 < SEQ) ? (u + 1) : (SEQ - 1);
        xbuf[u] = xq[(size_t)idx * BATCH * 4];
    }

    // ---- fill: ticks 0..7 (guarded) ----
#pragma unroll
    for (int u = 0; u < UF; ++u) {
        const int k = u;
        const int pidx = (k + 1 + UF < SEQ) ? (k + 1 + UF) : (SEQ - 1);
        tick<true>(k, s, xbuf[u], xq + (size_t)pidx * BATCH * 4, out);
    }

    // ---- main: ticks 8..2031, guard-free ----
#pragma unroll 1
    for (int kc = UF; kc < 2032; kc += UF) {
        const float* xb = xq + (size_t)(kc + 1 + UF) * BATCH * 4;
#pragma unroll
        for (int u = 0; u < UF; ++u)
            tick<false>(kc + u, s, xbuf[u], xb + (size_t)u * BATCH * 4, out);
    }

    // ---- drain: ticks 2032..2055 (guarded) ----
#pragma unroll 1
    for (int kc = 2032; kc < 2032 + 3 * UF; kc += UF) {
#pragma unroll
        for (int u = 0; u < UF; ++u) {
            const int k = kc + u;
            const int pidx = (k + 1 + UF < SEQ) ? (k + 1 + UF) : (SEQ - 1);
            tick<true>(k, s, xbuf[u], xq + (size_t)pidx * BATCH * 4, out);
        }
    }
}

extern "C" void kernel_launch(void* const* d_in, const int* in_sizes, int n_in,
                              void* d_out, int out_size) {
    const float* x     = (const float*)d_in[0];
    const float* w_ih  = (const float*)d_in[1];
    const float* w_hh  = (const float*)d_in[2];
    const float* b_ih  = (const float*)d_in[3];
    const float* b_hh  = (const float*)d_in[4];
    const float* reg_w = (const float*)d_in[5];
    const float* reg_b = (const float*)d_in[6];
    float* out = (float*)d_out;

    lstm_reg_kernel<<<128, 256>>>(x, w_ih, w_hh, b_ih, b_hh, reg_w, reg_b, out);
}